// round 3
// baseline (speedup 1.0000x reference)
#include <cuda_runtime.h>
#include <cstdint>

// Problem constants (fixed by setup_inputs)
#define BATCH 4
#define NPTS  16384
#define NTOT  (BATCH * NPTS)   // 65536
#define NJ    1024
#define CCOND 69
#define HID   256
#define TOPK  5

// Scratch (device globals; no dynamic allocation allowed)
__device__ float4 gPack[BATCH * HID];      // (w1x, w1y, w1z, base_b)  per (b, t)
__device__ float  gW2p[HID * 8];           // W2 row t padded to 8 floats
__device__ float  gRr[BATCH * 9];          // root-orient rotation per batch
__device__ float  gAux[BATCH * 4];         // s, t0, t1, t2
__device__ float  gT[BATCH * NJ * 12];     // top 3x4 rows of final transforms

// ---------------------------------------------------------------------------
// Rodrigues exactly as reference: angle = |a + 1e-8| (eps in norm only),
// axis = a/angle, quat = (cos(h), sin(h)*axis), quat re-normalized in quat2mat.
// ---------------------------------------------------------------------------
__device__ __forceinline__ void rodrigues_mat(float a0, float a1, float a2, float* R) {
    float e0 = a0 + 1e-8f, e1 = a1 + 1e-8f, e2 = a2 + 1e-8f;
    float angle = sqrtf(e0 * e0 + e1 * e1 + e2 * e2);
    float half = 0.5f * angle;
    float s = sinf(half), c = cosf(half);
    float inv = 1.0f / angle;
    float qw = c, qx = s * a0 * inv, qy = s * a1 * inv, qz = s * a2 * inv;
    float qn = rsqrtf(qw * qw + qx * qx + qy * qy + qz * qz);
    qw *= qn; qx *= qn; qy *= qn; qz *= qn;
    float w2 = qw * qw, x2 = qx * qx, y2 = qy * qy, z2 = qz * qz;
    float wx = qw * qx, wy = qw * qy, wz = qw * qz;
    float xy = qx * qy, xz = qx * qz, yz = qy * qz;
    R[0] = w2 + x2 - y2 - z2; R[1] = 2.f * xy - 2.f * wz; R[2] = 2.f * wy + 2.f * xz;
    R[3] = 2.f * wz + 2.f * xy; R[4] = w2 - x2 + y2 - z2; R[5] = 2.f * yz - 2.f * wx;
    R[6] = 2.f * xz - 2.f * wy; R[7] = 2.f * wx + 2.f * yz; R[8] = w2 - x2 - y2 + z2;
}

// ---------------------------------------------------------------------------
// Kernel A: base[b][t] = b1[t] + cond[b] . W1[3:, t].  FULLY UNROLLED so all
// 69 strided W1 loads are in flight at once (R2 post-mortem: unroll 1 gave
// MLP=1 -> 38us).  Grid: (BATCH) blocks x HID threads.
// ---------------------------------------------------------------------------
__global__ void prep_kernel(const float* __restrict__ cond,
                            const float* __restrict__ W1,
                            const float* __restrict__ b1,
                            const float* __restrict__ W2,
                            const float* __restrict__ root,
                            const float* __restrict__ trans,
                            const float* __restrict__ scale) {
    int b = blockIdx.x;
    int t = threadIdx.x;
    const float* cb = cond + b * CCOND;

    // Gather all products first (independent loads, deep MLP), then reduce.
    float prod[CCOND];
    #pragma unroll
    for (int c = 0; c < CCOND; c++)
        prod[c] = cb[c] * W1[(3 + c) * HID + t];
    float acc = b1[t];
    #pragma unroll
    for (int c = 0; c < CCOND; c++)
        acc += prod[c];

    gPack[b * HID + t] = make_float4(W1[t], W1[HID + t], W1[2 * HID + t], acc);

    if (b == 0) {
        #pragma unroll
        for (int o = 0; o < 6; o++) gW2p[t * 8 + o] = W2[t * 6 + o];
        gW2p[t * 8 + 6] = 0.f;
        gW2p[t * 8 + 7] = 0.f;
    }
    if (t == 0) {
        float R[9];
        rodrigues_mat(root[b * 3], root[b * 3 + 1], root[b * 3 + 2], R);
        #pragma unroll
        for (int i = 0; i < 9; i++) gRr[b * 9 + i] = R[i];
        gAux[b * 4 + 0] = scale[b];
        gAux[b * 4 + 1] = trans[b * 3 + 0];
        gAux[b * 4 + 2] = trans[b * 3 + 1];
        gAux[b * 4 + 3] = trans[b * 3 + 2];
    }
}

// ---------------------------------------------------------------------------
// Kernel B: warp per (b, j). Lane covers 8 hidden units (t = lane + 32*i).
// tf6 = sum_t relu(base + n.w1[t]) * W2[t, :]; then Rodrigues + compose with
// root transform + scale + translation. Stores 3x4 rows to gT.
// ---------------------------------------------------------------------------
__global__ void tmat_kernel(const float* __restrict__ nodes,
                            const float* __restrict__ b2) {
    int gw = (blockIdx.x * blockDim.x + threadIdx.x) >> 5;  // 0..4095
    int lane = threadIdx.x & 31;
    int b = gw >> 10;
    int j = gw & (NJ - 1);

    float n0 = nodes[j * 3], n1 = nodes[j * 3 + 1], n2 = nodes[j * 3 + 2];
    float a0 = 0.f, a1 = 0.f, a2 = 0.f, a3 = 0.f, a4 = 0.f, a5 = 0.f;

    #pragma unroll
    for (int i = 0; i < 8; i++) {
        int t = lane + (i << 5);
        float4 p = gPack[(b << 8) + t];
        float h = fmaf(n0, p.x, fmaf(n1, p.y, fmaf(n2, p.z, p.w)));
        h = fmaxf(h, 0.f);
        const float4* w2v = (const float4*)(gW2p + t * 8);
        float4 lo = w2v[0];
        float4 hi = w2v[1];
        a0 = fmaf(h, lo.x, a0); a1 = fmaf(h, lo.y, a1); a2 = fmaf(h, lo.z, a2);
        a3 = fmaf(h, lo.w, a3); a4 = fmaf(h, hi.x, a4); a5 = fmaf(h, hi.y, a5);
    }
    #pragma unroll
    for (int off = 16; off; off >>= 1) {
        a0 += __shfl_xor_sync(0xffffffffu, a0, off);
        a1 += __shfl_xor_sync(0xffffffffu, a1, off);
        a2 += __shfl_xor_sync(0xffffffffu, a2, off);
        a3 += __shfl_xor_sync(0xffffffffu, a3, off);
        a4 += __shfl_xor_sync(0xffffffffu, a4, off);
        a5 += __shfl_xor_sync(0xffffffffu, a5, off);
    }
    if (lane == 0) {
        float r0 = a0 + b2[0], r1 = a1 + b2[1], r2 = a2 + b2[2];
        float u0 = a3 + b2[3], u1 = a4 + b2[4], u2 = a5 + b2[5];
        float R[9];
        rodrigues_mat(r0, r1, r2, R);
        const float* Rr = gRr + b * 9;
        float s = gAux[b * 4];
        float tr[3] = {gAux[b * 4 + 1], gAux[b * 4 + 2], gAux[b * 4 + 3]};
        float M[12];
        #pragma unroll
        for (int r = 0; r < 3; r++) {
            float c0 = Rr[r * 3], c1 = Rr[r * 3 + 1], c2 = Rr[r * 3 + 2];
            M[r * 4 + 0] = s * (c0 * R[0] + c1 * R[3] + c2 * R[6]);
            M[r * 4 + 1] = s * (c0 * R[1] + c1 * R[4] + c2 * R[7]);
            M[r * 4 + 2] = s * (c0 * R[2] + c1 * R[5] + c2 * R[8]);
            M[r * 4 + 3] = s * (c0 * u0 + c1 * u1 + c2 * u2) + tr[r] * s;
        }
        float4* dst = (float4*)(gT + ((size_t)((b << 10) + j)) * 12);
        dst[0] = make_float4(M[0], M[1], M[2], M[3]);
        dst[1] = make_float4(M[4], M[5], M[6], M[7]);
        dst[2] = make_float4(M[8], M[9], M[10], M[11]);
    }
}

// ---------------------------------------------------------------------------
// Kernel C: TWO points per thread (pA = base+tid, pB = pA + NTOT/2) so each
// shared-mem candidate load (LDS.128 broadcast) feeds 6 FMAs instead of 3.
// Metric = |x|^2-shifted squared distance (ordering-invariant): 3 FMA/cand.
// Sorted top-5 in registers, rarely-taken insertion branch per point.
// Grid: 256 blocks x 128 threads.
// ---------------------------------------------------------------------------
__global__ void knn_kernel(const float* __restrict__ x,
                           const float* __restrict__ nodes,
                           float* __restrict__ out) {
    __shared__ float4 sn[NJ];
    int tid = threadIdx.x;
    for (int e = tid; e < NJ; e += 128) {
        float v0 = nodes[e * 3], v1 = nodes[e * 3 + 1], v2 = nodes[e * 3 + 2];
        sn[e] = make_float4(-2.f * v0, -2.f * v1, -2.f * v2,
                            v0 * v0 + v1 * v1 + v2 * v2);
    }
    __syncthreads();

    int pA = blockIdx.x * 128 + tid;          // 0..32767
    int pB = pA + (NTOT / 2);                 // 32768..65535

    float ax = x[pA * 3], ay = x[pA * 3 + 1], az = x[pA * 3 + 2];
    float bx = x[pB * 3], by = x[pB * 3 + 1], bz = x[pB * 3 + 2];

    float Ad0 = 1e30f, Ad1 = 1e30f, Ad2 = 1e30f, Ad3 = 1e30f, Ad4 = 1e30f;
    int   Ai0 = 0, Ai1 = 0, Ai2 = 0, Ai3 = 0, Ai4 = 0;
    float Bd0 = 1e30f, Bd1 = 1e30f, Bd2 = 1e30f, Bd3 = 1e30f, Bd4 = 1e30f;
    int   Bi0 = 0, Bi1 = 0, Bi2 = 0, Bi3 = 0, Bi4 = 0;

    #pragma unroll 8
    for (int j = 0; j < NJ; j++) {
        float4 q = sn[j];
        float ta = fmaf(ax, q.x, fmaf(ay, q.y, fmaf(az, q.z, q.w)));
        float tb = fmaf(bx, q.x, fmaf(by, q.y, fmaf(bz, q.z, q.w)));
        if (ta < Ad4) {
            bool c3 = ta < Ad3, c2 = ta < Ad2, c1 = ta < Ad1, c0 = ta < Ad0;
            Ad4 = c3 ? Ad3 : ta;               Ai4 = c3 ? Ai3 : j;
            Ad3 = c3 ? (c2 ? Ad2 : ta) : Ad3;  Ai3 = c3 ? (c2 ? Ai2 : j) : Ai3;
            Ad2 = c2 ? (c1 ? Ad1 : ta) : Ad2;  Ai2 = c2 ? (c1 ? Ai1 : j) : Ai2;
            Ad1 = c1 ? (c0 ? Ad0 : ta) : Ad1;  Ai1 = c1 ? (c0 ? Ai0 : j) : Ai1;
            Ad0 = c0 ? ta : Ad0;               Ai0 = c0 ? j : Ai0;
        }
        if (tb < Bd4) {
            bool c3 = tb < Bd3, c2 = tb < Bd2, c1 = tb < Bd1, c0 = tb < Bd0;
            Bd4 = c3 ? Bd3 : tb;               Bi4 = c3 ? Bi3 : j;
            Bd3 = c3 ? (c2 ? Bd2 : tb) : Bd3;  Bi3 = c3 ? (c2 ? Bi2 : j) : Bi3;
            Bd2 = c2 ? (c1 ? Bd1 : tb) : Bd2;  Bi2 = c2 ? (c1 ? Bi1 : j) : Bi2;
            Bd1 = c1 ? (c0 ? Bd0 : tb) : Bd1;  Bi1 = c1 ? (c0 ? Bi0 : j) : Bi1;
            Bd0 = c0 ? tb : Bd0;               Bi0 = c0 ? j : Bi0;
        }
    }

    // finalize both points
    {
        float dv[TOPK] = {Ad0, Ad1, Ad2, Ad3, Ad4};
        int   iv[TOPK] = {Ai0, Ai1, Ai2, Ai3, Ai4};
        int b = pA >> 14;
        float xx = ax * ax + ay * ay + az * az;
        float wsum = 0.f, o0 = 0.f, o1 = 0.f, o2 = 0.f;
        #pragma unroll
        for (int k = 0; k < TOPK; k++) {
            float dd = fmaxf(dv[k] + xx, 0.f);
            float dist = sqrtf(dd);
            float wk = -logf(fminf(dist, 1.f) - 1e-6f);
            wsum += wk;
            const float4* Tp = (const float4*)(gT + ((size_t)((b << 10) + iv[k])) * 12);
            float4 r0 = Tp[0], r1 = Tp[1], r2 = Tp[2];
            o0 = fmaf(wk, fmaf(r0.x, ax, fmaf(r0.y, ay, fmaf(r0.z, az, r0.w))), o0);
            o1 = fmaf(wk, fmaf(r1.x, ax, fmaf(r1.y, ay, fmaf(r1.z, az, r1.w))), o1);
            o2 = fmaf(wk, fmaf(r2.x, ax, fmaf(r2.y, ay, fmaf(r2.z, az, r2.w))), o2);
        }
        float inv = 1.f / wsum;
        out[pA * 3 + 0] = o0 * inv;
        out[pA * 3 + 1] = o1 * inv;
        out[pA * 3 + 2] = o2 * inv;
    }
    {
        float dv[TOPK] = {Bd0, Bd1, Bd2, Bd3, Bd4};
        int   iv[TOPK] = {Bi0, Bi1, Bi2, Bi3, Bi4};
        int b = pB >> 14;
        float xx = bx * bx + by * by + bz * bz;
        float wsum = 0.f, o0 = 0.f, o1 = 0.f, o2 = 0.f;
        #pragma unroll
        for (int k = 0; k < TOPK; k++) {
            float dd = fmaxf(dv[k] + xx, 0.f);
            float dist = sqrtf(dd);
            float wk = -logf(fminf(dist, 1.f) - 1e-6f);
            wsum += wk;
            const float4* Tp = (const float4*)(gT + ((size_t)((b << 10) + iv[k])) * 12);
            float4 r0 = Tp[0], r1 = Tp[1], r2 = Tp[2];
            o0 = fmaf(wk, fmaf(r0.x, bx, fmaf(r0.y, by, fmaf(r0.z, bz, r0.w))), o0);
            o1 = fmaf(wk, fmaf(r1.x, bx, fmaf(r1.y, by, fmaf(r1.z, bz, r1.w))), o1);
            o2 = fmaf(wk, fmaf(r2.x, bx, fmaf(r2.y, bz * 0.f + by, fmaf(r2.z, bz, r2.w))), o2);
        }
        float inv = 1.f / wsum;
        out[pB * 3 + 0] = o0 * inv;
        out[pB * 3 + 1] = o1 * inv;
        out[pB * 3 + 2] = o2 * inv;
    }
}

// ---------------------------------------------------------------------------
// Inputs (metadata order): x, cond_smpl, nodes, smpl_root_orient, smpl_trans,
// scale, W1, b1, W2, b2.  Output: float32 (B, N, 3).
// ---------------------------------------------------------------------------
extern "C" void kernel_launch(void* const* d_in, const int* in_sizes, int n_in,
                              void* d_out, int out_size) {
    const float* x     = (const float*)d_in[0];
    const float* cond  = (const float*)d_in[1];
    const float* nodes = (const float*)d_in[2];
    const float* root  = (const float*)d_in[3];
    const float* trans = (const float*)d_in[4];
    const float* scale = (const float*)d_in[5];
    const float* W1    = (const float*)d_in[6];
    const float* b1    = (const float*)d_in[7];
    const float* W2    = (const float*)d_in[8];
    const float* b2    = (const float*)d_in[9];
    float* out = (float*)d_out;

    prep_kernel<<<BATCH, HID>>>(cond, W1, b1, W2, root, trans, scale);
    tmat_kernel<<<(BATCH * NJ * 32) / 256, 256>>>(nodes, b2);
    knn_kernel<<<(NTOT / 2) / 128, 128>>>(x, nodes, out);
}

// round 4
// speedup vs baseline: 1.2624x; 1.2624x over previous
#include <cuda_runtime.h>
#include <cstdint>

// Problem constants (fixed by setup_inputs)
#define BATCH 4
#define NPTS  16384
#define NTOT  (BATCH * NPTS)   // 65536
#define NJ    1024
#define CCOND 69
#define HID   256
#define TOPK  5

// Scratch (device globals; no dynamic allocation allowed)
__device__ float4 gPack[BATCH * HID];      // (w1x, w1y, w1z, base_b)  per (b, t)
__device__ float  gW2p[HID * 8];           // W2 row t padded to 8 floats
__device__ float  gRr[BATCH * 9];          // root-orient rotation per batch
__device__ float  gAux[BATCH * 4];         // s, t0, t1, t2
__device__ float  gT[BATCH * NJ * 12];     // top 3x4 rows of final transforms

// ---------------------------------------------------------------------------
// Rodrigues exactly as reference: angle = |a + 1e-8| (eps in norm only),
// axis = a/angle, quat = (cos(h), sin(h)*axis), quat re-normalized in quat2mat.
// ---------------------------------------------------------------------------
__device__ __forceinline__ void rodrigues_mat(float a0, float a1, float a2, float* R) {
    float e0 = a0 + 1e-8f, e1 = a1 + 1e-8f, e2 = a2 + 1e-8f;
    float angle = sqrtf(e0 * e0 + e1 * e1 + e2 * e2);
    float half = 0.5f * angle;
    float s = sinf(half), c = cosf(half);
    float inv = 1.0f / angle;
    float qw = c, qx = s * a0 * inv, qy = s * a1 * inv, qz = s * a2 * inv;
    float qn = rsqrtf(qw * qw + qx * qx + qy * qy + qz * qz);
    qw *= qn; qx *= qn; qy *= qn; qz *= qn;
    float w2 = qw * qw, x2 = qx * qx, y2 = qy * qy, z2 = qz * qz;
    float wx = qw * qx, wy = qw * qy, wz = qw * qz;
    float xy = qx * qy, xz = qx * qz, yz = qy * qz;
    R[0] = w2 + x2 - y2 - z2; R[1] = 2.f * xy - 2.f * wz; R[2] = 2.f * wy + 2.f * xz;
    R[3] = 2.f * wz + 2.f * xy; R[4] = w2 - x2 + y2 - z2; R[5] = 2.f * yz - 2.f * wx;
    R[6] = 2.f * xz - 2.f * wy; R[7] = 2.f * wx + 2.f * yz; R[8] = w2 - x2 - y2 + z2;
}

// ---------------------------------------------------------------------------
// Kernel A: base[b][t] = b1[t] + cond[b] . W1[3:, t].
// R3 post-mortem: prod[69] array spilled at 32 regs. Now: fully unrolled loop
// with 4 round-robin scalar accumulators -> no register-indexed array, deep
// independent-load window without spills.
// ---------------------------------------------------------------------------
__global__ __launch_bounds__(HID) void prep_kernel(
        const float* __restrict__ cond,
        const float* __restrict__ W1,
        const float* __restrict__ b1,
        const float* __restrict__ W2,
        const float* __restrict__ root,
        const float* __restrict__ trans,
        const float* __restrict__ scale) {
    int b = blockIdx.x;
    int t = threadIdx.x;
    const float* cb = cond + b * CCOND;

    float s0 = 0.f, s1 = 0.f, s2 = 0.f, s3 = 0.f;
    #pragma unroll
    for (int c = 0; c < CCOND; c += 4) {
        s0 = fmaf(cb[c], W1[(3 + c) * HID + t], s0);
        if (c + 1 < CCOND) s1 = fmaf(cb[c + 1], W1[(4 + c) * HID + t], s1);
        if (c + 2 < CCOND) s2 = fmaf(cb[c + 2], W1[(5 + c) * HID + t], s2);
        if (c + 3 < CCOND) s3 = fmaf(cb[c + 3], W1[(6 + c) * HID + t], s3);
    }
    float acc = b1[t] + ((s0 + s1) + (s2 + s3));

    gPack[b * HID + t] = make_float4(W1[t], W1[HID + t], W1[2 * HID + t], acc);

    if (b == 0) {
        #pragma unroll
        for (int o = 0; o < 6; o++) gW2p[t * 8 + o] = W2[t * 6 + o];
        gW2p[t * 8 + 6] = 0.f;
        gW2p[t * 8 + 7] = 0.f;
    }
    if (t == 0) {
        float R[9];
        rodrigues_mat(root[b * 3], root[b * 3 + 1], root[b * 3 + 2], R);
        #pragma unroll
        for (int i = 0; i < 9; i++) gRr[b * 9 + i] = R[i];
        gAux[b * 4 + 0] = scale[b];
        gAux[b * 4 + 1] = trans[b * 3 + 0];
        gAux[b * 4 + 2] = trans[b * 3 + 1];
        gAux[b * 4 + 3] = trans[b * 3 + 2];
    }
}

// ---------------------------------------------------------------------------
// Kernel B: warp per (b, j). Lane covers 8 hidden units (t = lane + 32*i).
// tf6 = sum_t relu(base + n.w1[t]) * W2[t, :]; then Rodrigues + compose with
// root transform + scale + translation. Stores 3x4 rows to gT.
// ---------------------------------------------------------------------------
__global__ void tmat_kernel(const float* __restrict__ nodes,
                            const float* __restrict__ b2) {
    int gw = (blockIdx.x * blockDim.x + threadIdx.x) >> 5;  // 0..4095
    int lane = threadIdx.x & 31;
    int b = gw >> 10;
    int j = gw & (NJ - 1);

    float n0 = nodes[j * 3], n1 = nodes[j * 3 + 1], n2 = nodes[j * 3 + 2];
    float a0 = 0.f, a1 = 0.f, a2 = 0.f, a3 = 0.f, a4 = 0.f, a5 = 0.f;

    #pragma unroll
    for (int i = 0; i < 8; i++) {
        int t = lane + (i << 5);
        float4 p = gPack[(b << 8) + t];
        float h = fmaf(n0, p.x, fmaf(n1, p.y, fmaf(n2, p.z, p.w)));
        h = fmaxf(h, 0.f);
        const float4* w2v = (const float4*)(gW2p + t * 8);
        float4 lo = w2v[0];
        float4 hi = w2v[1];
        a0 = fmaf(h, lo.x, a0); a1 = fmaf(h, lo.y, a1); a2 = fmaf(h, lo.z, a2);
        a3 = fmaf(h, lo.w, a3); a4 = fmaf(h, hi.x, a4); a5 = fmaf(h, hi.y, a5);
    }
    #pragma unroll
    for (int off = 16; off; off >>= 1) {
        a0 += __shfl_xor_sync(0xffffffffu, a0, off);
        a1 += __shfl_xor_sync(0xffffffffu, a1, off);
        a2 += __shfl_xor_sync(0xffffffffu, a2, off);
        a3 += __shfl_xor_sync(0xffffffffu, a3, off);
        a4 += __shfl_xor_sync(0xffffffffu, a4, off);
        a5 += __shfl_xor_sync(0xffffffffu, a5, off);
    }
    if (lane == 0) {
        float r0 = a0 + b2[0], r1 = a1 + b2[1], r2 = a2 + b2[2];
        float u0 = a3 + b2[3], u1 = a4 + b2[4], u2 = a5 + b2[5];
        float R[9];
        rodrigues_mat(r0, r1, r2, R);
        const float* Rr = gRr + b * 9;
        float s = gAux[b * 4];
        float tr[3] = {gAux[b * 4 + 1], gAux[b * 4 + 2], gAux[b * 4 + 3]};
        float M[12];
        #pragma unroll
        for (int r = 0; r < 3; r++) {
            float c0 = Rr[r * 3], c1 = Rr[r * 3 + 1], c2 = Rr[r * 3 + 2];
            M[r * 4 + 0] = s * (c0 * R[0] + c1 * R[3] + c2 * R[6]);
            M[r * 4 + 1] = s * (c0 * R[1] + c1 * R[4] + c2 * R[7]);
            M[r * 4 + 2] = s * (c0 * R[2] + c1 * R[5] + c2 * R[8]);
            M[r * 4 + 3] = s * (c0 * u0 + c1 * u1 + c2 * u2) + tr[r] * s;
        }
        float4* dst = (float4*)(gT + ((size_t)((b << 10) + j)) * 12);
        dst[0] = make_float4(M[0], M[1], M[2], M[3]);
        dst[1] = make_float4(M[4], M[5], M[6], M[7]);
        dst[2] = make_float4(M[8], M[9], M[10], M[11]);
    }
}

// ---------------------------------------------------------------------------
// Kernel C (exact R2 version, known 40us): per point. Nodes in smem as
// (-2n, |n|^2); metric = |x|^2-shifted squared distance (ordering-invariant)
// -> 3 FMA/candidate. Sorted top-5 in registers, rarely-taken insertion
// branch. Then weights + blend of 5 gathered 3x4 transforms (L2-resident).
// Grid: 512 blocks x 128 threads.
// ---------------------------------------------------------------------------
__global__ void knn_kernel(const float* __restrict__ x,
                           const float* __restrict__ nodes,
                           float* __restrict__ out) {
    __shared__ float4 sn[NJ];
    int tid = threadIdx.x;
    for (int e = tid; e < NJ; e += 128) {
        float v0 = nodes[e * 3], v1 = nodes[e * 3 + 1], v2 = nodes[e * 3 + 2];
        sn[e] = make_float4(-2.f * v0, -2.f * v1, -2.f * v2,
                            v0 * v0 + v1 * v1 + v2 * v2);
    }
    __syncthreads();

    int p = blockIdx.x * 128 + tid;      // 0..65535
    int b = p >> 14;                     // NPTS = 16384
    float x0 = x[p * 3], x1 = x[p * 3 + 1], x2 = x[p * 3 + 2];
    float xx = x0 * x0 + x1 * x1 + x2 * x2;

    float d0 = 1e30f, d1 = 1e30f, d2 = 1e30f, d3 = 1e30f, d4 = 1e30f;
    int   i0 = 0, i1 = 0, i2 = 0, i3 = 0, i4 = 0;

    #pragma unroll 8
    for (int j = 0; j < NJ; j++) {
        float4 q = sn[j];
        float t = fmaf(x0, q.x, fmaf(x1, q.y, fmaf(x2, q.z, q.w)));
        if (t < d4) {
            bool c3 = t < d3, c2 = t < d2, c1 = t < d1, c0 = t < d0;
            d4 = c3 ? d3 : t;               i4 = c3 ? i3 : j;
            d3 = c3 ? (c2 ? d2 : t) : d3;   i3 = c3 ? (c2 ? i2 : j) : i3;
            d2 = c2 ? (c1 ? d1 : t) : d2;   i2 = c2 ? (c1 ? i1 : j) : i2;
            d1 = c1 ? (c0 ? d0 : t) : d1;   i1 = c1 ? (c0 ? i0 : j) : i1;
            d0 = c0 ? t : d0;               i0 = c0 ? j : i0;
        }
    }

    float dv[TOPK] = {d0, d1, d2, d3, d4};
    int   iv[TOPK] = {i0, i1, i2, i3, i4};

    float wsum = 0.f, o0 = 0.f, o1 = 0.f, o2 = 0.f;
    #pragma unroll
    for (int k = 0; k < TOPK; k++) {
        float dd = fmaxf(dv[k] + xx, 0.f);
        float dist = sqrtf(dd);
        float wk = -logf(fminf(dist, 1.f) - 1e-6f);
        wsum += wk;
        const float4* Tp = (const float4*)(gT + ((size_t)((b << 10) + iv[k])) * 12);
        float4 r0 = Tp[0], r1 = Tp[1], r2 = Tp[2];
        o0 = fmaf(wk, fmaf(r0.x, x0, fmaf(r0.y, x1, fmaf(r0.z, x2, r0.w))), o0);
        o1 = fmaf(wk, fmaf(r1.x, x0, fmaf(r1.y, x1, fmaf(r1.z, x2, r1.w))), o1);
        o2 = fmaf(wk, fmaf(r2.x, x0, fmaf(r2.y, x1, fmaf(r2.z, x2, r2.w))), o2);
    }
    float inv = 1.f / wsum;
    out[p * 3 + 0] = o0 * inv;
    out[p * 3 + 1] = o1 * inv;
    out[p * 3 + 2] = o2 * inv;
}

// ---------------------------------------------------------------------------
// Inputs (metadata order): x, cond_smpl, nodes, smpl_root_orient, smpl_trans,
// scale, W1, b1, W2, b2.  Output: float32 (B, N, 3).
// ---------------------------------------------------------------------------
extern "C" void kernel_launch(void* const* d_in, const int* in_sizes, int n_in,
                              void* d_out, int out_size) {
    const float* x     = (const float*)d_in[0];
    const float* cond  = (const float*)d_in[1];
    const float* nodes = (const float*)d_in[2];
    const float* root  = (const float*)d_in[3];
    const float* trans = (const float*)d_in[4];
    const float* scale = (const float*)d_in[5];
    const float* W1    = (const float*)d_in[6];
    const float* b1    = (const float*)d_in[7];
    const float* W2    = (const float*)d_in[8];
    const float* b2    = (const float*)d_in[9];
    float* out = (float*)d_out;

    prep_kernel<<<BATCH, HID>>>(cond, W1, b1, W2, root, trans, scale);
    tmat_kernel<<<(BATCH * NJ * 32) / 256, 256>>>(nodes, b2);
    knn_kernel<<<NTOT / 128, 128>>>(x, nodes, out);
}